// round 17
// baseline (speedup 1.0000x reference)
#include <cuda_runtime.h>
#include <cuda_fp16.h>
#include <math.h>
#include <stdint.h>

#define NN 8192
#define DD 512
#define CHUNKS 8         // K chunks of 64 fp16 (128B)
#define ROWB 1024        // bytes per packed fp16 row (512 * 2)

// fp16 copy of X (contiguous row-major), filled by prep_kernel each call
__device__ __align__(128) __half g_P[(size_t)NN * DD];
// softplus variance per row (applied to cov diagonal by diag tiles)
__device__ float g_diag[NN];

// ---------------- helpers ----------------
__device__ __forceinline__ uint32_t smem_u32(const void* p) {
    uint32_t a;
    asm("{ .reg .u64 t; cvta.to.shared.u64 t, %1; cvt.u32.u64 %0, t; }"
        : "=r"(a) : "l"(p));
    return a;
}
__device__ __forceinline__ void cp_async16(uint32_t sa, const void* ga) {
    asm volatile("cp.async.cg.shared.global [%0], [%1], 16;" :: "r"(sa), "l"(ga));
}
#define LDSM4(r0, r1, r2, r3, ad) \
    asm volatile("ldmatrix.sync.aligned.m8n8.x4.shared.b16 {%0,%1,%2,%3}, [%4];" \
                 : "=r"(r0), "=r"(r1), "=r"(r2), "=r"(r3) : "r"(ad))

#define MMA_F16(d, a, b) \
    asm volatile("mma.sync.aligned.m16n8k16.row.col.f32.f16.f16.f32 " \
                 "{%0,%1,%2,%3}, {%4,%5,%6,%7}, {%8,%9}, {%0,%1,%2,%3};" \
                 : "+f"((d)[0]), "+f"((d)[1]), "+f"((d)[2]), "+f"((d)[3]) \
                 : "r"((a)[0]), "r"((a)[1]), "r"((a)[2]), "r"((a)[3]), \
                   "r"((b)[0]), "r"((b)[1]))

#define MBAR_INIT(mb, c) asm volatile("mbarrier.init.shared.b64 [%0], %1;" :: "r"(mb), "r"(c) : "memory")
#define MBAR_ARRIVE(mb)  asm volatile("mbarrier.arrive.shared.b64 _, [%0];" :: "r"(mb) : "memory")
// .noinc is load-bearing: without it each async arrival also increments the
// pending count (count-neutral) and the barrier phase never completes.
#define CPASYNC_MBAR_ARRIVE(mb) \
    asm volatile("cp.async.mbarrier.arrive.noinc.shared.b64 [%0];" :: "r"(mb) : "memory")

__device__ __forceinline__ void mbar_wait(uint32_t mb, uint32_t parity) {
    uint32_t done;
    asm volatile(
        "{\n\t.reg .pred p;\n\t"
        "mbarrier.try_wait.parity.shared.b64 p, [%1], %2;\n\t"
        "selp.b32 %0, 1, 0, p;\n\t}"
        : "=r"(done) : "r"(mb), "r"(parity) : "memory");
    if (!done) {
        asm volatile(
            "{\n\t.reg .pred P1;\n\t"
            "WL_%=:\n\t"
            "mbarrier.try_wait.parity.shared.b64 P1, [%0], %1, 0x989680;\n\t"
            "@P1 bra.uni WD_%=;\n\t"
            "bra.uni WL_%=;\n\t"
            "WD_%=:\n\t}"
            :: "r"(mb), "r"(parity) : "memory");
    }
}

// ---------------- fused pre-pass ----------------
__global__ void __launch_bounds__(256)
prep_kernel(const float* __restrict__ X,
            const float* __restrict__ muK,
            const float* __restrict__ varK,
            const float* __restrict__ muB,
            const float* __restrict__ varB,
            float* __restrict__ outMu)
{
    const int row  = blockIdx.x * 8 + (threadIdx.x >> 5);
    const int lane = threadIdx.x & 31;

    const float* xr = X + (size_t)row * DD;
    char* prow = (char*)g_P + (size_t)row * ROWB;

    float smu = 0.0f, sv = 0.0f;
#pragma unroll
    for (int j = 0; j < 4; j++) {
        const int k = lane * 4 + j * 128;
        const float4 xv = *(const float4*)(xr + k);
        const float4 m  = *(const float4*)(muK + k);
        const float4 v  = *(const float4*)(varK + k);
        smu = fmaf(xv.x, m.x, smu); smu = fmaf(xv.y, m.y, smu);
        smu = fmaf(xv.z, m.z, smu); smu = fmaf(xv.w, m.w, smu);
        sv  = fmaf(xv.x, v.x, sv);  sv  = fmaf(xv.y, v.y, sv);
        sv  = fmaf(xv.z, v.z, sv);  sv  = fmaf(xv.w, v.w, sv);

        __half2 p0 = __floats2half2_rn(xv.x, xv.y);
        __half2 p1 = __floats2half2_rn(xv.z, xv.w);
        uint2 w;
        w.x = *(uint32_t*)&p0;
        w.y = *(uint32_t*)&p1;
        *(uint2*)(prow + k * 2) = w;
    }
#pragma unroll
    for (int o = 16; o; o >>= 1) {
        smu += __shfl_xor_sync(0xFFFFFFFFu, smu, o);
        sv  += __shfl_xor_sync(0xFFFFFFFFu, sv, o);
    }
    if (lane == 0) {
        outMu[row] = smu + __ldg(muB);
        const float z = sv + __ldg(varB);
        g_diag[row] = log1pf(expf(z)) + 1e-8f;
    }
}

// ---------------- paired-tile GEMM, producer-warp specialized ----------------
// 288 threads: warps 0-7 compute (wg = warp>>2 selects half tile; 2x2 of 64x64
// within each half); warp 8 streams cp.async chunks and arms mbarriers.
#define SUBT 16384
#define HSTG (3 * SUBT)                 // A | B-left | B-right per stage (48K)
#define NSTAGE 3
#define CTRL (NSTAGE * HSTG)            // mbar block offset (147456)
#define SMEM_BYTES (1024 + CTRL + 64)   // 148544
#define EPIT 132
#define HALF_STG_BYTES (128 * EPIT * 4) // 67584 per half

__global__ void __launch_bounds__(288, 1)
xxt_hmma_kernel(const float* __restrict__ rho_k, float* __restrict__ C)
{
    // decode pair-index -> (r, c0, has2) over upper triangle of 64x64 tiles
    const int bid = blockIdx.x;
    float disc = 4225.0f - 4.0f * (float)bid;
    int t = (int)((65.0f - sqrtf(disc)) * 0.5f);
    if (t < 0) t = 0;
    if (t > 31) t = 31;
    while (t > 0 && t * (65 - t) > bid) t--;
    while ((t + 1) * (65 - (t + 1)) <= bid) t++;
    const int rem = bid - t * (65 - t);
    const int m   = 32 - t;
    const int r   = 2 * t + (rem >= m ? 1 : 0);
    const int jj0 = rem - (rem >= m ? m : 0);
    const int c0  = r + 2 * jj0;
    const bool has2  = (c0 + 1) < 64;
    const bool diagL = (c0 == r);

    extern __shared__ char sm_raw[];
    const uint32_t raw  = smem_u32(sm_raw);
    const uint32_t base = (raw + 1023) & ~1023u;
    const uint32_t ctrl = base + CTRL;

    const int tid  = threadIdx.x;
    const int lane = tid & 31;
    const int warp = tid >> 5;

    const int R0 = r * 128;

    // mbarriers: full[s] (32 producer arrivals), empty[s] (256 consumer arrivals)
    if (tid == 0) {
#pragma unroll
        for (int s = 0; s < NSTAGE; s++) {
            MBAR_INIT(ctrl + s * 8, 32);
            MBAR_INIT(ctrl + 24 + s * 8, 256);
        }
    }
    __syncthreads();

    const char* gp = (const char*)g_P;

    if (warp == 8) {
        // ---------------- producer ----------------
        const char* gA  = gp + (size_t)R0 * ROWB;
        const char* gBL = gp + (size_t)(c0 * 128) * ROWB;
        const char* gBR = gp + (size_t)((c0 + 1) * 128) * ROWB;

        int pe[3] = {0, 0, 0};   // empty-barrier phase per stage
        for (int c = 0; c < CHUNKS; c++) {
            const int s = (c >= 6) ? (c - 6) : (c >= 3 ? c - 3 : c);
            if (c >= 3) { mbar_wait(ctrl + 24 + s * 8, (uint32_t)pe[s]); pe[s] ^= 1; }
            const uint32_t sA = base + s * HSTG;
            const size_t cofs = (size_t)c * 128;
#pragma unroll 1
            for (int i = 0; i < 32; i++) {
                const int idx  = i * 32 + lane;
                const int row  = idx >> 3;
                const int unit = idx & 7;
                const uint32_t so = (uint32_t)(row * 128 + ((unit ^ (row & 7)) << 4));
                const size_t gofs = (size_t)row * ROWB + cofs + unit * 16;
                cp_async16(sA + so, gA + gofs);
                if (!diagL) cp_async16(sA + SUBT + so, gBL + gofs);
                if (has2)   cp_async16(sA + 2 * SUBT + so, gBR + gofs);
            }
            CPASYNC_MBAR_ARRIVE(ctrl + s * 8);
        }
    }

    float acc[4][8][4];
    const int wg = warp >> 2;            // 0 left half, 1 right half
    const int wr = (warp >> 1) & 1;
    const int wc = warp & 1;
    const int hl = lane >> 4;
    const int l15 = lane & 15;
    const int Ccol = (c0 + (wg & 1)) * 128;
    const bool active = (warp < 8) && ((wg == 0) || has2);

    if (warp < 8) {
        // ---------------- consumers ----------------
#pragma unroll
        for (int i = 0; i < 4; i++)
#pragma unroll
            for (int j = 0; j < 8; j++)
#pragma unroll
                for (int k = 0; k < 4; k++) acc[i][j][k] = 0.0f;

        int rowOffA[4], r7A[4], rowOffB[4], r7B[4];
#pragma unroll
        for (int i = 0; i < 4; i++) {
            const int ra = wr * 64 + i * 16 + l15;
            const int rb = wc * 64 + i * 16 + l15;
            rowOffA[i] = ra * 128; r7A[i] = ra & 7;
            rowOffB[i] = rb * 128; r7B[i] = rb & 7;
        }
        const uint32_t bOffB = (wg == 1) ? 2u * SUBT : (diagL ? 0u : (uint32_t)SUBT);

#pragma unroll
        for (int c = 0; c < CHUNKS; c++) {
            const int s = c % NSTAGE;                    // constant after unroll
            const uint32_t pf = (uint32_t)((c / 3) & 1); // full parity
            mbar_wait(ctrl + s * 8, pf);

            const uint32_t bA = base + s * HSTG;
            const uint32_t bB = bA + bOffB;

#pragma unroll
            for (int ks = 0; ks < 4; ks++) {
                const int u = ks * 2 + hl;
                uint32_t aF[4][4], bF[8][2];
#pragma unroll
                for (int mi = 0; mi < 4; mi++) {
                    const uint32_t ad = bA + rowOffA[mi] + ((u ^ r7A[mi]) << 4);
                    LDSM4(aF[mi][0], aF[mi][1], aF[mi][2], aF[mi][3], ad);
                }
#pragma unroll
                for (int bj = 0; bj < 4; bj++) {
                    const uint32_t ad = bB + rowOffB[bj] + ((u ^ r7B[bj]) << 4);
                    uint32_t t0, t1, t2, t3;
                    LDSM4(t0, t1, t2, t3, ad);
                    bF[2 * bj][0] = t0; bF[2 * bj + 1][0] = t1;
                    bF[2 * bj][1] = t2; bF[2 * bj + 1][1] = t3;
                }
#pragma unroll
                for (int mi = 0; mi < 4; mi++)
#pragma unroll
                    for (int nj = 0; nj < 8; nj++)
                        MMA_F16(acc[mi][nj], aF[mi], bF[nj]);
            }
            MBAR_ARRIVE(ctrl + 24 + s * 8);
        }
    }

    // ---------------- epilogue (coalesced via per-half smem staging) ----------------
    const float s = __ldg(rho_k);
    float* stage = (float*)(sm_raw + (base - raw) + (wg & 1) * HALF_STG_BYTES);

    __syncthreads();   // producer done, all consumption done; smem reusable

    // ---- pass 1: upper tiles, direct layout ----
    if (active) {
#pragma unroll
        for (int mi = 0; mi < 4; mi++) {
#pragma unroll
            for (int nj = 0; nj < 8; nj++) {
                const int rr  = wr * 64 + mi * 16 + (lane >> 2);
                const int col = wc * 64 + nj * 8 + (lane & 3) * 2;
                float2 v0 = make_float2(acc[mi][nj][0] * s, acc[mi][nj][1] * s);
                float2 v1 = make_float2(acc[mi][nj][2] * s, acc[mi][nj][3] * s);
                *(float2*)&stage[(size_t)rr * EPIT + col]       = v0;
                *(float2*)&stage[(size_t)(rr + 8) * EPIT + col] = v1;
            }
        }
    }
    __syncthreads();
    if (active) {
#pragma unroll 4
        for (int i = 0; i < 32; i++) {
            const int row = (warp & 3) * 32 + i;
            float4 v = *(float4*)&stage[(size_t)row * EPIT + lane * 4];
            *(float4*)&C[(size_t)(R0 + row) * NN + Ccol + lane * 4] = v;
        }
    }

    __syncthreads();   // upper writes done (ordering for diag patch)

    const bool mirror = active && !((wg == 0) && diagL);

    // ---- pass 2: mirror tiles, transposed layout ----
    if (mirror) {
#pragma unroll
        for (int mi = 0; mi < 4; mi++) {
#pragma unroll
            for (int nj = 0; nj < 8; nj++) {
                const int rr = wr * 64 + mi * 16 + (lane >> 2);
                const int cc = wc * 64 + nj * 8 + (lane & 3) * 2;
                stage[(size_t)(cc + 0) * EPIT + rr]     = acc[mi][nj][0] * s;
                stage[(size_t)(cc + 1) * EPIT + rr]     = acc[mi][nj][1] * s;
                stage[(size_t)(cc + 0) * EPIT + rr + 8] = acc[mi][nj][2] * s;
                stage[(size_t)(cc + 1) * EPIT + rr + 8] = acc[mi][nj][3] * s;
            }
        }
    }
    __syncthreads();
    if (mirror) {
#pragma unroll 4
        for (int i = 0; i < 32; i++) {
            const int mm = (warp & 3) * 32 + i;
            float4 v = *(float4*)&stage[(size_t)mm * EPIT + lane * 4];
            *(float4*)&C[(size_t)(Ccol + mm) * NN + R0 + lane * 4] = v;
        }
    } else if (diagL && tid < 128) {
        // patch the covariance diagonal with the softplus variance
        const int rr = R0 + tid;
        C[(size_t)rr * NN + rr] = g_diag[rr];
    }
}

extern "C" void kernel_launch(void* const* d_in, const int* in_sizes, int n_in,
                              void* d_out, int out_size)
{
    const float* x     = (const float*)d_in[0];
    const float* mu_k  = (const float*)d_in[1];
    const float* rho_k = (const float*)d_in[2];
    const float* var_k = (const float*)d_in[3];
    const float* mu_b  = (const float*)d_in[4];
    const float* var_b = (const float*)d_in[5];

    float* out_mu = (float*)d_out;
    float* cov    = out_mu + NN;

    cudaFuncSetAttribute(xxt_hmma_kernel,
                         cudaFuncAttributeMaxDynamicSharedMemorySize, SMEM_BYTES);

    prep_kernel<<<NN / 8, 256>>>(x, mu_k, var_k, mu_b, var_b, out_mu);
    xxt_hmma_kernel<<<1056, 288, SMEM_BYTES>>>(rho_k, cov);
}